// round 8
// baseline (speedup 1.0000x reference)
#include <cuda_runtime.h>
#include <cuda_bf16.h>

// LengthRegulator: expand x[b,s,:] by duration[b,s] along time, then mask.
// out layout: [B*max_mel*E] floats, then [B*max_mel] mask floats (0.0/1.0).

#define B_CONST 32
#define S_CONST 1024
#define MAX_MEL_CAP (S_CONST * 8)

__device__ int g_idx[B_CONST * MAX_MEL_CAP];

// One CTA, 32 warps; warp w handles batch w. Each lane scans 32 durations in
// registers, warp-scans lane totals (shfl), then directly writes the inverted
// index map g_idx[b][t] = source position (or -1 past mel_len). No block-wide
// barriers in the scan itself.
__global__ void scan_build_kernel(const void* __restrict__ dur_raw,
                                  int S, int max_mel) {
    __shared__ int use64_sh;
    int tid = threadIdx.x;
    int w = tid >> 5, l = tid & 31;

    const long long* d64 = (const long long*)dur_raw;
    const int*       d32 = (const int*)dur_raw;

    // Dtype detect (first 512 int64 words only: in-bounds either way).
    // Durations lie in [0,8); int32 read as int64 is out-of-range w.h.p.
    if (w == 0) {
        int ok = 1;
        for (int i = l; i < 512; i += 32) {
            long long v = d64[i];
            if (v < 0 || v >= 8) ok = 0;
        }
        unsigned ballot = __ballot_sync(0xffffffffu, ok);
        if (l == 0) use64_sh = (ballot == 0xffffffffu) ? 1 : 0;
    }
    __syncthreads();
    int use64 = use64_sh;

    int b = w;
    int base = b * S + l * 32;
    int d[32];
    if (use64) {
        #pragma unroll
        for (int i = 0; i < 32; i++) d[i] = (int)d64[base + i];
    } else {
        const int4* p = (const int4*)(d32 + base);
        #pragma unroll
        for (int i = 0; i < 8; i++) {
            int4 v = p[i];
            d[i*4+0] = v.x; d[i*4+1] = v.y; d[i*4+2] = v.z; d[i*4+3] = v.w;
        }
    }

    int sum = 0;
    #pragma unroll
    for (int i = 0; i < 32; i++) sum += d[i];

    // inclusive warp scan of lane sums
    int pre = sum;
    #pragma unroll
    for (int off = 1; off < 32; off <<= 1) {
        int v = __shfl_up_sync(0xffffffffu, pre, off);
        if (l >= off) pre += v;
    }
    int total = __shfl_sync(0xffffffffu, pre, 31);   // mel_len for batch b
    int c0 = pre - sum;                              // exclusive prefix

    int* idx = g_idx + b * max_mel;
    int j = c0;
    #pragma unroll
    for (int i = 0; i < 32; i++) {
        int s_pos = l * 32 + i;
        for (int k = 0; k < d[i]; k++) idx[j++] = s_pos;
    }
    for (int j2 = total + l; j2 < max_mel; j2 += 32) idx[j2] = -1;
}

// One warp per output row (256 floats): each lane moves 2 float4 (32 B).
// blockIdx.y = batch. Streaming stores keep L2 free for x gather reuse.
__global__ void fill_kernel(const float* __restrict__ x,
                            float* __restrict__ out,
                            float* __restrict__ mask,
                            int S, int max_mel) {
    int t = blockIdx.x * 8 + (threadIdx.x >> 5);
    if (t >= max_mel) return;
    int lane = threadIdx.x & 31;
    int b = blockIdx.y;

    int row = b * max_mel + t;
    int s = __ldg(g_idx + row);

    float4* out4 = reinterpret_cast<float4*>(out) + row * 64;
    if (s < 0) {
        float4 z = make_float4(0.f, 0.f, 0.f, 0.f);
        __stcs(out4 + lane, z);
        __stcs(out4 + lane + 32, z);
        if (lane == 0) mask[row] = 1.0f;
    } else {
        const float4* src = reinterpret_cast<const float4*>(x)
                            + (b * S + s) * 64;
        float4 v0 = __ldg(src + lane);
        float4 v1 = __ldg(src + lane + 32);
        __stcs(out4 + lane, v0);
        __stcs(out4 + lane + 32, v1);
        if (lane == 0) mask[row] = 0.0f;
    }
}

extern "C" void kernel_launch(void* const* d_in, const int* in_sizes, int n_in,
                              void* d_out, int out_size) {
    const float* x = (const float*)d_in[0];

    const int B = B_CONST;
    const int E = in_sizes[0] / in_sizes[1];     // 256
    const int S = in_sizes[1] / B;               // 1024
    const int max_mel = out_size / (B * (E + 1));

    float* out = (float*)d_out;
    float* mask = out + (long long)B * max_mel * E;

    scan_build_kernel<<<1, 1024>>>(d_in[1], S, max_mel);

    dim3 grid((max_mel + 7) / 8, B);
    fill_kernel<<<grid, 256>>>(x, out, mask, S, max_mel);
}

// round 9
// speedup vs baseline: 5.2940x; 5.2940x over previous
#include <cuda_runtime.h>
#include <cuda_bf16.h>

// LengthRegulator: expand x[b,s,:] by duration[b,s] along time, then mask.
// out layout: [B*max_mel*E] floats, then [B*max_mel] mask floats (0.0/1.0).

#define B_CONST 32
#define S_CONST 1024
#define MAX_MEL_CAP (S_CONST * 8)

__device__ int g_idx[B_CONST * MAX_MEL_CAP];

// One CTA per batch, 1024 threads. Thread t owns duration[b][t]:
// warp scan + cross-warp smem scan (2 barriers), then every thread writes its
// own [c0, c0+d) index slots and a strided -1 tail. Fully parallel build.
__global__ void scan_build_kernel(const void* __restrict__ dur_raw,
                                  int S, int max_mel) {
    __shared__ int warp_tot[32];
    int b = blockIdx.x;
    int t = threadIdx.x;
    int w = t >> 5, l = t & 31;

    const long long* d64 = (const long long*)dur_raw;
    const int*       d32 = (const int*)dur_raw;

    // Dtype detect from first 512 int64 words only (in-bounds either way).
    // Durations lie in [0,8); int32 read as int64 is out-of-range w.h.p.
    int ok = 1;
    if (t < 512) {
        long long v = d64[t];
        ok = (v >= 0 && v < 8) ? 1 : 0;
    }
    int use64 = __syncthreads_and(ok);

    int d = use64 ? (int)d64[b * S + t] : d32[b * S + t];

    // inclusive warp scan
    int pre = d;
    #pragma unroll
    for (int off = 1; off < 32; off <<= 1) {
        int v = __shfl_up_sync(0xffffffffu, pre, off);
        if (l >= off) pre += v;
    }
    if (l == 31) warp_tot[w] = pre;
    __syncthreads();
    if (w == 0) {
        int v = warp_tot[l];
        int p = v;
        #pragma unroll
        for (int off = 1; off < 32; off <<= 1) {
            int q = __shfl_up_sync(0xffffffffu, p, off);
            if (l >= off) p += q;
        }
        warp_tot[l] = p - v;   // exclusive warp offsets
        if (l == 31) warp_tot[31] = p - v;  // same thing; total = p when l==31
    }
    __syncthreads();
    int c0 = warp_tot[w] + pre - d;        // exclusive prefix of thread t
    // mel_len = exclusive offset of last warp + its inclusive last = compute via reduction:
    __shared__ int mel_sh;
    if (t == S_CONST - 1) mel_sh = c0 + d;
    __syncthreads();
    int mel = mel_sh;

    int* idx = g_idx + b * max_mel;
    for (int k = 0; k < d; k++) idx[c0 + k] = t;
    for (int j = mel + t; j < max_mel; j += S_CONST) idx[j] = -1;
}

// 4 rows per warp, 8 warps per block => 32 rows/block. Each lane moves 2
// float4 per row; all 8 loads issued before stores (MLP). blockIdx.y = batch.
__global__ void fill_kernel(const float* __restrict__ x,
                            float* __restrict__ out,
                            float* __restrict__ mask,
                            int S, int max_mel) {
    int warp = threadIdx.x >> 5;
    int lane = threadIdx.x & 31;
    int t0 = (blockIdx.x * 8 + warp) * 4;
    if (t0 >= max_mel) return;
    int b = blockIdx.y;
    int row0 = b * max_mel + t0;

    // rows are 4-aligned; fetch 4 indices at once, broadcast
    int4 iv;
    if (lane == 0) iv = *reinterpret_cast<const int4*>(g_idx + row0);
    iv.x = __shfl_sync(0xffffffffu, iv.x, 0);
    iv.y = __shfl_sync(0xffffffffu, iv.y, 0);
    iv.z = __shfl_sync(0xffffffffu, iv.z, 0);
    iv.w = __shfl_sync(0xffffffffu, iv.w, 0);
    int sidx[4] = {iv.x, iv.y, iv.z, iv.w};

    const float4* xb = reinterpret_cast<const float4*>(x) + b * S * 64;
    float4 v0[4], v1[4];
    #pragma unroll
    for (int r = 0; r < 4; r++) {
        if (sidx[r] >= 0) {
            const float4* src = xb + sidx[r] * 64;
            v0[r] = __ldg(src + lane);
            v1[r] = __ldg(src + lane + 32);
        } else {
            v0[r] = make_float4(0.f, 0.f, 0.f, 0.f);
            v1[r] = v0[r];
        }
    }
    float4* out4 = reinterpret_cast<float4*>(out) + row0 * 64;
    #pragma unroll
    for (int r = 0; r < 4; r++) {
        __stcs(out4 + r * 64 + lane, v0[r]);
        __stcs(out4 + r * 64 + lane + 32, v1[r]);
    }
    if (lane < 4) mask[row0 + lane] = (sidx[lane] < 0) ? 1.0f : 0.0f;
}

extern "C" void kernel_launch(void* const* d_in, const int* in_sizes, int n_in,
                              void* d_out, int out_size) {
    const float* x = (const float*)d_in[0];

    const int B = B_CONST;
    const int E = in_sizes[0] / in_sizes[1];     // 256
    const int S = in_sizes[1] / B;               // 1024
    const int max_mel = out_size / (B * (E + 1));

    float* out = (float*)d_out;
    float* mask = out + (long long)B * max_mel * E;

    scan_build_kernel<<<B, S_CONST>>>(d_in[1], S, max_mel);

    dim3 grid((max_mel + 31) / 32, B);
    fill_kernel<<<grid, 256>>>(x, out, mask, S, max_mel);
}